// round 7
// baseline (speedup 1.0000x reference)
#include <cuda_runtime.h>
#include <cuda_fp16.h>
#include <cuda_bf16.h>
#include <cstdint>
#include <cstddef>

#define N_ROWS 4096
#define D 512
#define TWO_N 8192
#define T_DROP 409
#define CHUNKS 8              // 512 / 64 K-elems per chunk
#define PANEL_BYTES 16384     // 128 rows x 128 bytes (64 bf16)
#define CAND_CAP 2048
#define FIX_SCALE 1099511627776.0   // 2^40

// ---------------- device scratch (allocation-free rule) ----------------
__device__ __align__(1024) uint16_t g_Gp[(size_t)TWO_N * D];      // bf16 SW128 panels (8 MB)
__device__ __align__(16)   uint16_t g_S16[(size_t)TWO_N * TWO_N]; // fp16 Gram (128 MB)
__device__ float g_rowlog[TWO_N];
__device__ float g_diag[N_ROWS];                                  // S[i, 4096+i]
__device__ double g_part[32];

// ---------------- PTX helpers ----------------
__device__ __forceinline__ uint32_t smem_u32(const void* p) {
    uint32_t a;
    asm("{ .reg .u64 t; cvta.to.shared.u64 t, %1; cvt.u32.u64 %0, t; }" : "=r"(a) : "l"(p));
    return a;
}
__device__ __forceinline__ void cp16(uint32_t saddr, const void* g) {
    asm volatile("cp.async.cg.shared.global [%0], [%1], 16;" :: "r"(saddr), "l"(g));
}
__device__ __forceinline__ void cp_commit() {
    asm volatile("cp.async.commit_group;" ::: "memory");
}
template <int N> __device__ __forceinline__ void cp_wait() {
    asm volatile("cp.async.wait_group %0;" :: "n"(N) : "memory");
}
__device__ __forceinline__ void ldsm4(uint32_t* r, uint32_t addr) {
    asm volatile("ldmatrix.sync.aligned.m8n8.x4.shared.b16 {%0,%1,%2,%3}, [%4];"
                 : "=r"(r[0]), "=r"(r[1]), "=r"(r[2]), "=r"(r[3]) : "r"(addr));
}
__device__ __forceinline__ void mma16816(float* d, const uint32_t* a, const uint32_t* b) {
    asm volatile(
        "mma.sync.aligned.m16n8k16.row.col.f32.bf16.bf16.f32 "
        "{%0,%1,%2,%3}, {%4,%5,%6,%7}, {%8,%9}, {%0,%1,%2,%3};"
        : "+f"(d[0]), "+f"(d[1]), "+f"(d[2]), "+f"(d[3])
        : "r"(a[0]), "r"(a[1]), "r"(a[2]), "r"(a[3]), "r"(b[0]), "r"(b[1]));
}
__device__ __forceinline__ uint32_t swz128(uint32_t off) { return off ^ ((off >> 3) & 0x70); }

// ---------------------------------------------------------------------------
// 1) Row L2-normalize into bf16 SW128-swizzled panels.
// ---------------------------------------------------------------------------
__global__ __launch_bounds__(128) void normalize_kernel(const float* __restrict__ h1,
                                                        const float* __restrict__ h2) {
    int half_ = threadIdx.x >> 6;
    int g     = threadIdx.x & 63;
    int row   = blockIdx.x * 2 + half_;
    const float* src = (row < N_ROWS) ? (h1 + (size_t)row * D)
                                      : (h2 + (size_t)(row - N_ROWS) * D);
    float4 v0 = ((const float4*)src)[g * 2];
    float4 v1 = ((const float4*)src)[g * 2 + 1];
    float ss = v0.x * v0.x + v0.y * v0.y + v0.z * v0.z + v0.w * v0.w
             + v1.x * v1.x + v1.y * v1.y + v1.z * v1.z + v1.w * v1.w;
#pragma unroll
    for (int o = 16; o; o >>= 1) ss += __shfl_xor_sync(0xffffffffu, ss, o);
    __shared__ float ws[4];
    if ((threadIdx.x & 31) == 0) ws[threadIdx.x >> 5] = ss;
    __syncthreads();
    float tot = ws[half_ * 2] + ws[half_ * 2 + 1];
    float inv = 1.0f / fmaxf(sqrtf(tot), 1e-12f);

    __nv_bfloat162 b0 = __floats2bfloat162_rn(v0.x * inv, v0.y * inv);
    __nv_bfloat162 b1 = __floats2bfloat162_rn(v0.z * inv, v0.w * inv);
    __nv_bfloat162 b2 = __floats2bfloat162_rn(v1.x * inv, v1.y * inv);
    __nv_bfloat162 b3 = __floats2bfloat162_rn(v1.z * inv, v1.w * inv);
    uint4 w;
    w.x = *reinterpret_cast<uint32_t*>(&b0);
    w.y = *reinterpret_cast<uint32_t*>(&b1);
    w.z = *reinterpret_cast<uint32_t*>(&b2);
    w.w = *reinterpret_cast<uint32_t*>(&b3);

    int kc = g >> 3, gi = g & 7;
    size_t panel = ((size_t)(row >> 7) * CHUNKS + kc) * PANEL_BYTES;
    uint32_t off = swz128((uint32_t)(row & 127) * 128 + gi * 16);
    *reinterpret_cast<uint4*>(reinterpret_cast<char*>(g_Gp) + panel + off) = w;
}

// ---------------------------------------------------------------------------
// 2) S = G*G^T via mma.sync bf16 (128x128 tiles, symmetric: bx >= by only).
// ---------------------------------------------------------------------------
#define SMEM_GEMM 65536
#define STAGE_LD 130   // fp16 stage tile row stride (conflict-free transpose reads)

__global__ __launch_bounds__(256, 2) void gram_mma_kernel() {
    extern __shared__ __align__(1024) char smc[];
    int bx = blockIdx.x, by = blockIdx.y;
    if (bx < by) return;

    uint32_t sb = smem_u32(smc);
    int tid = threadIdx.x, wid = tid >> 5, lane = tid & 31;
    int mOff = (wid & 3) * 32;     // warp M offset in tile
    int nOff = (wid >> 2) * 64;    // warp N offset in tile

    const char* Ap = reinterpret_cast<const char*>(g_Gp) + (size_t)by * CHUNKS * PANEL_BYTES;
    const char* Bp = reinterpret_cast<const char*>(g_Gp) + (size_t)bx * CHUNKS * PANEL_BYTES;

    auto copy_chunk = [&](int c, int buf) {
        uint32_t sA = sb + buf * 16384;
        uint32_t sB = sb + 32768 + buf * 16384;
        const char* gA = Ap + (size_t)c * PANEL_BYTES;
        const char* gB = Bp + (size_t)c * PANEL_BYTES;
#pragma unroll
        for (int i = 0; i < 4; i++) cp16(sA + (tid + i * 256) * 16, gA + (tid + i * 256) * 16);
#pragma unroll
        for (int i = 0; i < 4; i++) cp16(sB + (tid + i * 256) * 16, gB + (tid + i * 256) * 16);
        cp_commit();
    };

    // Per-lane ldmatrix address components (SW128: XOR = (row&7)*16, 16B granular)
    uint32_t offA[2], xorA[2];
#pragma unroll
    for (int mt = 0; mt < 2; mt++) {
        uint32_t r = mOff + mt * 16 + (lane & 15);
        offA[mt] = r * 128; xorA[mt] = (r & 7) * 16;
    }
    uint32_t colA = (lane >> 4) * 16;
    uint32_t offB[4], xorB[4];
#pragma unroll
    for (int nb = 0; nb < 4; nb++) {
        uint32_t r = nOff + nb * 16 + (lane & 7) + ((lane >> 4) << 3);
        offB[nb] = r * 128; xorB[nb] = (r & 7) * 16;
    }
    uint32_t colB = ((lane >> 3) & 1) * 16;

    float acc[2][8][4];
#pragma unroll
    for (int i = 0; i < 2; i++)
#pragma unroll
        for (int j = 0; j < 8; j++)
#pragma unroll
            for (int k = 0; k < 4; k++) acc[i][j][k] = 0.0f;

    copy_chunk(0, 0);
    copy_chunk(1, 1);

    for (int c = 0; c < CHUNKS; c++) {
        int buf = c & 1;
        if (c < CHUNKS - 1) cp_wait<1>(); else cp_wait<0>();
        __syncthreads();
        uint32_t sA = sb + buf * 16384;
        uint32_t sB = sb + 32768 + buf * 16384;
#pragma unroll
        for (int ks = 0; ks < 4; ks++) {
            uint32_t a[2][4], b[4][4];
#pragma unroll
            for (int mt = 0; mt < 2; mt++)
                ldsm4(a[mt], sA + offA[mt] + (((uint32_t)ks * 32 + colA) ^ xorA[mt]));
#pragma unroll
            for (int nb = 0; nb < 4; nb++)
                ldsm4(b[nb], sB + offB[nb] + (((uint32_t)ks * 32 + colB) ^ xorB[nb]));
#pragma unroll
            for (int mt = 0; mt < 2; mt++)
#pragma unroll
                for (int nb = 0; nb < 4; nb++) {
                    mma16816(acc[mt][nb * 2],     a[mt], &b[nb][0]);
                    mma16816(acc[mt][nb * 2 + 1], a[mt], &b[nb][2]);
                }
        }
        __syncthreads();
        if (c + 2 < CHUNKS) copy_chunk(c + 2, buf);
    }

    // ---- Epilogue: stage fp16 tile in smem, write tile (+ mirror) coalesced ----
    __half* st = reinterpret_cast<__half*>(smc);
    int rr = lane >> 2, cc = (lane & 3) * 2;
#pragma unroll
    for (int mt = 0; mt < 2; mt++)
#pragma unroll
        for (int nt = 0; nt < 8; nt++) {
            int r = mOff + mt * 16 + rr;
            int ccol = nOff + nt * 8 + cc;
            __half2 lo = __floats2half2_rn(acc[mt][nt][0], acc[mt][nt][1]);
            __half2 hi = __floats2half2_rn(acc[mt][nt][2], acc[mt][nt][3]);
            *reinterpret_cast<__half2*>(&st[r * STAGE_LD + ccol]) = lo;
            *reinterpret_cast<__half2*>(&st[(r + 8) * STAGE_LD + ccol]) = hi;
        }
    __syncthreads();

    // diag of s12: tile (by, bx=by+32) holds S[by*128+r][4096+by*128+r] at st[r][r]
    if (bx == by + 32) {
        for (int i = tid; i < 128; i += 256)
            g_diag[by * 128 + i] = __half2float(st[i * STAGE_LD + i]);
    }

    // direct tile: row-major coalesced
    for (int i = tid; i < 128 * 64; i += 256) {
        int r = i >> 6, cw = i & 63;
        uint32_t v = *reinterpret_cast<uint32_t*>(&st[r * STAGE_LD + cw * 2]);
        *reinterpret_cast<uint32_t*>(&g_S16[(size_t)(by * 128 + r) * TWO_N + bx * 128 + cw * 2]) = v;
    }
    if (bx > by) {
        // mirror: out[c][r] = tile[r][c]
        for (int i = tid; i < 128 * 64; i += 256) {
            int c = i >> 6, rw = i & 63;
            __half lo = st[(2 * rw) * STAGE_LD + c];
            __half hi = st[(2 * rw + 1) * STAGE_LD + c];
            __half2 v = __halves2half2(lo, hi);
            *reinterpret_cast<__half2*>(&g_S16[(size_t)(bx * 128 + c) * TWO_N + by * 128 + 2 * rw]) = v;
        }
    }
}

// ---------------------------------------------------------------------------
// 3) Per-row 16-bit radix select + exp-sum — 2 full sweeps.
//    Sweep 0: load/convert/store + top-byte hist.
//    Sweep 1 (fused): middle-bin exp-sum + boundary-bin low hists + stash.
//    Boundary contributions resolved from the small candidate buffer in
//    order-independent u64 fixed point (deterministic).
// ---------------------------------------------------------------------------
__device__ __forceinline__ uint32_t f2k16x2(uint32_t u) {
    uint32_t s = (u >> 15) & 0x00010001u;
    return u ^ (0x80008000u | (s * 0x7FFFu));
}
__device__ __forceinline__ float k2f16(uint32_t k) {
    uint32_t u = (k & 0x8000u) ? (k & 0x7FFFu) : ((~k) & 0xFFFFu);
    return __half2float(__ushort_as_half((unsigned short)u));
}
__device__ __forceinline__ void hist_add(uint32_t* h, uint32_t d, int lane) {
    unsigned m = __match_any_sync(0xffffffffu, d);
    if ((__ffs(m) - 1) == lane) atomicAdd(&h[d], (uint32_t)__popc(m));
}

__global__ __launch_bounds__(256) void row_select_kernel(const float* __restrict__ tau_ptr) {
    __shared__ __align__(16) uint32_t keys32[TWO_N / 2];   // 16 KB
    __shared__ uint32_t histT[256];
    __shared__ uint32_t scanT[256];
    __shared__ uint32_t lowA[256], lowB[256];
    __shared__ uint32_t cbuf[CAND_CAP];                    // 8 KB boundary-key stash
    __shared__ uint32_t nbuf;
    __shared__ uint32_t bc[12];
    __shared__ float fred[8];
    __shared__ unsigned long long pred_[8];
    int row = blockIdx.x, tid = threadIdx.x, lane = tid & 31;
    const uint4* rp4 = reinterpret_cast<const uint4*>(g_S16 + (size_t)row * TWO_N);

    histT[tid] = 0; lowA[tid] = 0; lowB[tid] = 0;
    if (tid == 0) nbuf = 0;
    __syncthreads();

    // ---- sweep 0: load + convert + store + top-byte histogram ----
    for (int i = tid; i < TWO_N / 8; i += 256) {
        uint4 w = rp4[i];
        uint32_t k0 = f2k16x2(w.x), k1 = f2k16x2(w.y), k2 = f2k16x2(w.z), k3 = f2k16x2(w.w);
        reinterpret_cast<uint4*>(keys32)[i] = make_uint4(k0, k1, k2, k3);
        hist_add(histT, (k0 >> 8) & 255u, lane);  hist_add(histT, k0 >> 24, lane);
        hist_add(histT, (k1 >> 8) & 255u, lane);  hist_add(histT, k1 >> 24, lane);
        hist_add(histT, (k2 >> 8) & 255u, lane);  hist_add(histT, k2 >> 24, lane);
        hist_add(histT, (k3 >> 8) & 255u, lane);  hist_add(histT, k3 >> 24, lane);
    }
    __syncthreads();

    // ---- suffix-scan the 256 top bins; locate both threshold bins ----
    scanT[tid] = histT[tid];
    __syncthreads();
#pragma unroll
    for (int stp = 1; stp < 256; stp <<= 1) {
        uint32_t v = scanT[tid] + ((tid + stp < 256) ? scanT[tid + stp] : 0u);
        __syncthreads();
        scanT[tid] = v;
        __syncthreads();
    }
    {
        const uint32_t KLO = TWO_N - T_DROP + 1;
        uint32_t mine = scanT[tid];
        uint32_t nxt  = (tid < 255) ? scanT[tid + 1] : 0u;
        if (mine >= T_DROP && nxt < T_DROP) { bc[0] = (uint32_t)tid; bc[1] = T_DROP - nxt; bc[8] = nxt; }
        if (mine >= KLO    && nxt < KLO)    { bc[2] = (uint32_t)tid; bc[3] = KLO - nxt;    bc[9] = nxt; }
    }
    __syncthreads();
    uint32_t dhi = bc[0], khi = bc[1], dlo = bc[2], klo = bc[3];
    uint32_t cntAbove = bc[8];   // # keys with top byte > dhi
    uint32_t cntAboveLo = bc[9]; // # keys with top byte > dlo

    float invtau = 1.0f / *tau_ptr;

    // ---- sweep 1 (fused): middle exp-sum + boundary low hists + stash ----
    float midsum = 0.0f;
    for (int i = tid; i < TWO_N / 8; i += 256) {
        uint4 w = reinterpret_cast<const uint4*>(keys32)[i];
#pragma unroll
        for (int j = 0; j < 4; j++) {
            uint32_t kk = (j == 0) ? w.x : (j == 1) ? w.y : (j == 2) ? w.z : w.w;
#pragma unroll
            for (int hh = 0; hh < 2; hh++) {
                uint32_t u = (hh == 0) ? (kk & 0xFFFFu) : (kk >> 16);
                uint32_t d = u >> 8;
                if (d > dlo && d < dhi) {
                    midsum += __expf(k2f16(u) * invtau);
                } else if (d == dhi || d == dlo) {
                    if (d == dhi) atomicAdd(&lowA[u & 255u], 1u);
                    if (d == dlo) atomicAdd(&lowB[u & 255u], 1u);
                    uint32_t idx = atomicAdd(&nbuf, 1u);
                    if (idx < CAND_CAP) cbuf[idx] = u;
                }
            }
        }
    }
    __syncthreads();

    // ---- low-byte suffix scans (bin dhi, then bin dlo) ----
    scanT[tid] = lowA[tid];
    __syncthreads();
#pragma unroll
    for (int stp = 1; stp < 256; stp <<= 1) {
        uint32_t v = scanT[tid] + ((tid + stp < 256) ? scanT[tid + stp] : 0u);
        __syncthreads();
        scanT[tid] = v;
        __syncthreads();
    }
    {
        uint32_t mine = scanT[tid], nxt = (tid < 255) ? scanT[tid + 1] : 0u;
        if (mine >= khi && nxt < khi) { bc[4] = (dhi << 8) | (uint32_t)tid; bc[6] = mine; }
    }
    __syncthreads();
    scanT[tid] = lowB[tid];
    __syncthreads();
#pragma unroll
    for (int stp = 1; stp < 256; stp <<= 1) {
        uint32_t v = scanT[tid] + ((tid + stp < 256) ? scanT[tid + stp] : 0u);
        __syncthreads();
        scanT[tid] = v;
        __syncthreads();
    }
    {
        uint32_t mine = scanT[tid], nxt = (tid < 255) ? scanT[tid + 1] : 0u;
        if (mine >= klo && nxt < klo) { bc[5] = (dlo << 8) | (uint32_t)tid; bc[7] = nxt; }
    }
    __syncthreads();
    uint32_t vhi = bc[4], vlo = bc[5];
    // counts, exactly as the old full-sweep definition:
    uint32_t cge = cntAbove + bc[6];                 // #(u >= vhi)
    uint32_t cle = TWO_N - cntAboveLo - bc[7];       // #(u <= vlo)

    // ---- boundary-bin contributions (order-independent u64 fixed point) ----
    unsigned long long part = 0ull;
    uint32_t nb_ = nbuf;
    if (nb_ <= CAND_CAP) {
        for (uint32_t i = tid; i < nb_; i += 256) {
            uint32_t u = cbuf[i];
            if (u > vlo && u < vhi)
                part += (unsigned long long)(__expf(k2f16(u) * invtau) * (float)FIX_SCALE);
        }
    } else {
        // fallback: rescan all keys for boundary bins (data-dependent, still deterministic)
        for (int i = tid; i < TWO_N / 8; i += 256) {
            uint4 w = reinterpret_cast<const uint4*>(keys32)[i];
#pragma unroll
            for (int j = 0; j < 4; j++) {
                uint32_t kk = (j == 0) ? w.x : (j == 1) ? w.y : (j == 2) ? w.z : w.w;
#pragma unroll
                for (int hh = 0; hh < 2; hh++) {
                    uint32_t u = (hh == 0) ? (kk & 0xFFFFu) : (kk >> 16);
                    uint32_t d = u >> 8;
                    if ((d == dhi || d == dlo) && u > vlo && u < vhi)
                        part += (unsigned long long)(__expf(k2f16(u) * invtau) * (float)FIX_SCALE);
                }
            }
        }
    }

    // ---- reduce: float middle sum + u64 boundary sum ----
#pragma unroll
    for (int o = 16; o; o >>= 1) {
        midsum += __shfl_xor_sync(0xffffffffu, midsum, o);
        part   += __shfl_xor_sync(0xffffffffu, part, o);
    }
    if (lane == 0) { fred[tid >> 5] = midsum; pred_[tid >> 5] = part; }
    __syncthreads();
    if (tid == 0) {
        float s = 0.0f; unsigned long long p = 0ull;
        for (int w = 0; w < 8; w++) { s += fred[w]; p += pred_[w]; }
        s += (float)((double)p * (1.0 / FIX_SCALE));
        s += (float)((int)cge - T_DROP) * __expf(k2f16(vhi) * invtau)
           + (float)((int)cle - T_DROP) * __expf(k2f16(vlo) * invtau);
        g_rowlog[row] = logf(s);
    }
}

// ---------------------------------------------------------------------------
// 4) Final reduction: 32-block partial + 1-warp finish
// ---------------------------------------------------------------------------
__global__ __launch_bounds__(128) void partial_kernel(const float* __restrict__ tau_ptr) {
    int tid = threadIdx.x, b = blockIdx.x;
    int i = b * 128 + tid;
    double invtau = 1.0 / (double)(*tau_ptr);
    double acc = 0.5 * ((double)g_rowlog[i] + (double)g_rowlog[N_ROWS + i])
               - (double)g_diag[i] * invtau;
#pragma unroll
    for (int o = 16; o; o >>= 1) acc += __shfl_xor_sync(0xffffffffu, acc, o);
    __shared__ double dred[4];
    if ((tid & 31) == 0) dred[tid >> 5] = acc;
    __syncthreads();
    if (tid == 0) g_part[b] = dred[0] + dred[1] + dred[2] + dred[3];
}

__global__ void finish_kernel(float* __restrict__ out) {
    int tid = threadIdx.x;  // 32
    double acc = g_part[tid];
#pragma unroll
    for (int o = 16; o; o >>= 1) acc += __shfl_xor_sync(0xffffffffu, acc, o);
    if (tid == 0) out[0] = (float)(acc / (double)N_ROWS);
}

// ---------------------------------------------------------------------------
extern "C" void kernel_launch(void* const* d_in, const int* in_sizes, int n_in,
                              void* d_out, int out_size) {
    const float* h1  = (const float*)d_in[0];
    const float* h2  = (const float*)d_in[1];
    const float* tau = (const float*)d_in[3];
    float* out = (float*)d_out;

    cudaFuncSetAttribute(gram_mma_kernel, cudaFuncAttributeMaxDynamicSharedMemorySize, SMEM_GEMM);

    normalize_kernel<<<TWO_N / 2, 128>>>(h1, h2);
    gram_mma_kernel<<<dim3(64, 64), 256, SMEM_GEMM>>>();
    row_select_kernel<<<TWO_N, 256>>>(tau);
    partial_kernel<<<32, 128>>>(tau);
    finish_kernel<<<1, 32>>>(out);
}

// round 8
// speedup vs baseline: 1.0108x; 1.0108x over previous
#include <cuda_runtime.h>
#include <cuda_fp16.h>
#include <cuda_bf16.h>
#include <cstdint>
#include <cstddef>

#define N_ROWS 4096
#define D 512
#define TWO_N 8192
#define T_DROP 409
#define CHUNKS 8              // 512 / 64 K-elems per chunk
#define PANEL_BYTES 16384     // 128 rows x 128 bytes (64 bf16)
#define CAND_CAP 2048
#define FIX_SCALE 1099511627776.0   // 2^40

// ---------------- device scratch (allocation-free rule) ----------------
__device__ __align__(1024) uint16_t g_Gp[(size_t)TWO_N * D];      // bf16 SW128 panels (8 MB)
__device__ __align__(16)   uint16_t g_S16[(size_t)TWO_N * TWO_N]; // fp16 Gram (128 MB)
__device__ float g_rowlog[TWO_N];
__device__ float g_diag[N_ROWS];                                  // S[i, 4096+i]
__device__ double g_part[32];

// ---------------- PTX helpers ----------------
__device__ __forceinline__ uint32_t smem_u32(const void* p) {
    uint32_t a;
    asm("{ .reg .u64 t; cvta.to.shared.u64 t, %1; cvt.u32.u64 %0, t; }" : "=r"(a) : "l"(p));
    return a;
}
__device__ __forceinline__ void cp16(uint32_t saddr, const void* g) {
    asm volatile("cp.async.cg.shared.global [%0], [%1], 16;" :: "r"(saddr), "l"(g));
}
__device__ __forceinline__ void cp_commit() {
    asm volatile("cp.async.commit_group;" ::: "memory");
}
template <int N> __device__ __forceinline__ void cp_wait() {
    asm volatile("cp.async.wait_group %0;" :: "n"(N) : "memory");
}
__device__ __forceinline__ void ldsm4(uint32_t* r, uint32_t addr) {
    asm volatile("ldmatrix.sync.aligned.m8n8.x4.shared.b16 {%0,%1,%2,%3}, [%4];"
                 : "=r"(r[0]), "=r"(r[1]), "=r"(r[2]), "=r"(r[3]) : "r"(addr));
}
__device__ __forceinline__ void mma16816(float* d, const uint32_t* a, const uint32_t* b) {
    asm volatile(
        "mma.sync.aligned.m16n8k16.row.col.f32.bf16.bf16.f32 "
        "{%0,%1,%2,%3}, {%4,%5,%6,%7}, {%8,%9}, {%0,%1,%2,%3};"
        : "+f"(d[0]), "+f"(d[1]), "+f"(d[2]), "+f"(d[3])
        : "r"(a[0]), "r"(a[1]), "r"(a[2]), "r"(a[3]), "r"(b[0]), "r"(b[1]));
}
__device__ __forceinline__ uint32_t swz128(uint32_t off) { return off ^ ((off >> 3) & 0x70); }

// ---------------------------------------------------------------------------
// 1) Row L2-normalize into bf16 SW128-swizzled panels.
// ---------------------------------------------------------------------------
__global__ __launch_bounds__(128) void normalize_kernel(const float* __restrict__ h1,
                                                        const float* __restrict__ h2) {
    int half_ = threadIdx.x >> 6;
    int g     = threadIdx.x & 63;
    int row   = blockIdx.x * 2 + half_;
    const float* src = (row < N_ROWS) ? (h1 + (size_t)row * D)
                                      : (h2 + (size_t)(row - N_ROWS) * D);
    float4 v0 = ((const float4*)src)[g * 2];
    float4 v1 = ((const float4*)src)[g * 2 + 1];
    float ss = v0.x * v0.x + v0.y * v0.y + v0.z * v0.z + v0.w * v0.w
             + v1.x * v1.x + v1.y * v1.y + v1.z * v1.z + v1.w * v1.w;
#pragma unroll
    for (int o = 16; o; o >>= 1) ss += __shfl_xor_sync(0xffffffffu, ss, o);
    __shared__ float ws[4];
    if ((threadIdx.x & 31) == 0) ws[threadIdx.x >> 5] = ss;
    __syncthreads();
    float tot = ws[half_ * 2] + ws[half_ * 2 + 1];
    float inv = 1.0f / fmaxf(sqrtf(tot), 1e-12f);

    __nv_bfloat162 b0 = __floats2bfloat162_rn(v0.x * inv, v0.y * inv);
    __nv_bfloat162 b1 = __floats2bfloat162_rn(v0.z * inv, v0.w * inv);
    __nv_bfloat162 b2 = __floats2bfloat162_rn(v1.x * inv, v1.y * inv);
    __nv_bfloat162 b3 = __floats2bfloat162_rn(v1.z * inv, v1.w * inv);
    uint4 w;
    w.x = *reinterpret_cast<uint32_t*>(&b0);
    w.y = *reinterpret_cast<uint32_t*>(&b1);
    w.z = *reinterpret_cast<uint32_t*>(&b2);
    w.w = *reinterpret_cast<uint32_t*>(&b3);

    int kc = g >> 3, gi = g & 7;
    size_t panel = ((size_t)(row >> 7) * CHUNKS + kc) * PANEL_BYTES;
    uint32_t off = swz128((uint32_t)(row & 127) * 128 + gi * 16);
    *reinterpret_cast<uint4*>(reinterpret_cast<char*>(g_Gp) + panel + off) = w;
}

// ---------------------------------------------------------------------------
// 2) S = G*G^T via mma.sync bf16 (128x128 tiles, symmetric: bx >= by only).
// ---------------------------------------------------------------------------
#define SMEM_GEMM 65536
#define STAGE_LD 130   // fp16 stage tile row stride (conflict-free transpose reads)

__global__ __launch_bounds__(256) void gram_mma_kernel() {
    extern __shared__ __align__(1024) char smc[];
    int bx = blockIdx.x, by = blockIdx.y;
    if (bx < by) return;

    uint32_t sb = smem_u32(smc);
    int tid = threadIdx.x, wid = tid >> 5, lane = tid & 31;
    int mOff = (wid & 3) * 32;     // warp M offset in tile
    int nOff = (wid >> 2) * 64;    // warp N offset in tile

    const char* Ap = reinterpret_cast<const char*>(g_Gp) + (size_t)by * CHUNKS * PANEL_BYTES;
    const char* Bp = reinterpret_cast<const char*>(g_Gp) + (size_t)bx * CHUNKS * PANEL_BYTES;

    auto copy_chunk = [&](int c, int buf) {
        uint32_t sA = sb + buf * 16384;
        uint32_t sB = sb + 32768 + buf * 16384;
        const char* gA = Ap + (size_t)c * PANEL_BYTES;
        const char* gB = Bp + (size_t)c * PANEL_BYTES;
#pragma unroll
        for (int i = 0; i < 4; i++) cp16(sA + (tid + i * 256) * 16, gA + (tid + i * 256) * 16);
#pragma unroll
        for (int i = 0; i < 4; i++) cp16(sB + (tid + i * 256) * 16, gB + (tid + i * 256) * 16);
        cp_commit();
    };

    // Per-lane ldmatrix address components (SW128: XOR = (row&7)*16, 16B granular)
    uint32_t offA[2], xorA[2];
#pragma unroll
    for (int mt = 0; mt < 2; mt++) {
        uint32_t r = mOff + mt * 16 + (lane & 15);
        offA[mt] = r * 128; xorA[mt] = (r & 7) * 16;
    }
    uint32_t colA = (lane >> 4) * 16;
    uint32_t offB[4], xorB[4];
#pragma unroll
    for (int nb = 0; nb < 4; nb++) {
        uint32_t r = nOff + nb * 16 + (lane & 7) + ((lane >> 4) << 3);
        offB[nb] = r * 128; xorB[nb] = (r & 7) * 16;
    }
    uint32_t colB = ((lane >> 3) & 1) * 16;

    float acc[2][8][4];
#pragma unroll
    for (int i = 0; i < 2; i++)
#pragma unroll
        for (int j = 0; j < 8; j++)
#pragma unroll
            for (int k = 0; k < 4; k++) acc[i][j][k] = 0.0f;

    copy_chunk(0, 0);
    copy_chunk(1, 1);

    for (int c = 0; c < CHUNKS; c++) {
        int buf = c & 1;
        if (c < CHUNKS - 1) cp_wait<1>(); else cp_wait<0>();
        __syncthreads();
        uint32_t sA = sb + buf * 16384;
        uint32_t sB = sb + 32768 + buf * 16384;
#pragma unroll
        for (int ks = 0; ks < 4; ks++) {
            uint32_t a[2][4], b[4][4];
#pragma unroll
            for (int mt = 0; mt < 2; mt++)
                ldsm4(a[mt], sA + offA[mt] + (((uint32_t)ks * 32 + colA) ^ xorA[mt]));
#pragma unroll
            for (int nb = 0; nb < 4; nb++)
                ldsm4(b[nb], sB + offB[nb] + (((uint32_t)ks * 32 + colB) ^ xorB[nb]));
#pragma unroll
            for (int mt = 0; mt < 2; mt++)
#pragma unroll
                for (int nb = 0; nb < 4; nb++) {
                    mma16816(acc[mt][nb * 2],     a[mt], &b[nb][0]);
                    mma16816(acc[mt][nb * 2 + 1], a[mt], &b[nb][2]);
                }
        }
        __syncthreads();
        if (c + 2 < CHUNKS) copy_chunk(c + 2, buf);
    }

    // ---- Epilogue: stage fp16 tile in smem, write tile (+ mirror) coalesced ----
    __half* st = reinterpret_cast<__half*>(smc);
    int rr = lane >> 2, cc = (lane & 3) * 2;
#pragma unroll
    for (int mt = 0; mt < 2; mt++)
#pragma unroll
        for (int nt = 0; nt < 8; nt++) {
            int r = mOff + mt * 16 + rr;
            int ccol = nOff + nt * 8 + cc;
            __half2 lo = __floats2half2_rn(acc[mt][nt][0], acc[mt][nt][1]);
            __half2 hi = __floats2half2_rn(acc[mt][nt][2], acc[mt][nt][3]);
            *reinterpret_cast<__half2*>(&st[r * STAGE_LD + ccol]) = lo;
            *reinterpret_cast<__half2*>(&st[(r + 8) * STAGE_LD + ccol]) = hi;
        }
    __syncthreads();

    // diag of s12: tile (by, bx=by+32) holds S[by*128+r][4096+by*128+r] at st[r][r]
    if (bx == by + 32) {
        for (int i = tid; i < 128; i += 256)
            g_diag[by * 128 + i] = __half2float(st[i * STAGE_LD + i]);
    }

    // direct tile: row-major coalesced
    for (int i = tid; i < 128 * 64; i += 256) {
        int r = i >> 6, cw = i & 63;
        uint32_t v = *reinterpret_cast<uint32_t*>(&st[r * STAGE_LD + cw * 2]);
        *reinterpret_cast<uint32_t*>(&g_S16[(size_t)(by * 128 + r) * TWO_N + bx * 128 + cw * 2]) = v;
    }
    if (bx > by) {
        // mirror: out[c][r] = tile[r][c]
        for (int i = tid; i < 128 * 64; i += 256) {
            int c = i >> 6, rw = i & 63;
            __half lo = st[(2 * rw) * STAGE_LD + c];
            __half hi = st[(2 * rw + 1) * STAGE_LD + c];
            __half2 v = __halves2half2(lo, hi);
            *reinterpret_cast<__half2*>(&g_S16[(size_t)(bx * 128 + c) * TWO_N + by * 128 + 2 * rw]) = v;
        }
    }
}

// ---------------------------------------------------------------------------
// 3) Per-row 16-bit radix select + exp-sum — 2 full sweeps (fused).
// ---------------------------------------------------------------------------
__device__ __forceinline__ uint32_t f2k16x2(uint32_t u) {
    uint32_t s = (u >> 15) & 0x00010001u;
    return u ^ (0x80008000u | (s * 0x7FFFu));
}
__device__ __forceinline__ float k2f16(uint32_t k) {
    uint32_t u = (k & 0x8000u) ? (k & 0x7FFFu) : ((~k) & 0xFFFFu);
    return __half2float(__ushort_as_half((unsigned short)u));
}
__device__ __forceinline__ void hist_add(uint32_t* h, uint32_t d, int lane) {
    unsigned m = __match_any_sync(0xffffffffu, d);
    if ((__ffs(m) - 1) == lane) atomicAdd(&h[d], (uint32_t)__popc(m));
}

__global__ __launch_bounds__(256) void row_select_kernel(const float* __restrict__ tau_ptr) {
    __shared__ __align__(16) uint32_t keys32[TWO_N / 2];   // 16 KB
    __shared__ uint32_t histT[256];
    __shared__ uint32_t scanT[256];
    __shared__ uint32_t lowA[256], lowB[256];
    __shared__ uint32_t cbuf[CAND_CAP];                    // 8 KB boundary-key stash
    __shared__ uint32_t nbuf;
    __shared__ uint32_t bc[12];
    __shared__ float fred[8];
    __shared__ unsigned long long pred_[8];
    int row = blockIdx.x, tid = threadIdx.x, lane = tid & 31;
    const uint4* rp4 = reinterpret_cast<const uint4*>(g_S16 + (size_t)row * TWO_N);

    histT[tid] = 0; lowA[tid] = 0; lowB[tid] = 0;
    if (tid == 0) nbuf = 0;
    __syncthreads();

    // ---- sweep 0: load + convert + store + top-byte histogram ----
    for (int i = tid; i < TWO_N / 8; i += 256) {
        uint4 w = rp4[i];
        uint32_t k0 = f2k16x2(w.x), k1 = f2k16x2(w.y), k2 = f2k16x2(w.z), k3 = f2k16x2(w.w);
        reinterpret_cast<uint4*>(keys32)[i] = make_uint4(k0, k1, k2, k3);
        hist_add(histT, (k0 >> 8) & 255u, lane);  hist_add(histT, k0 >> 24, lane);
        hist_add(histT, (k1 >> 8) & 255u, lane);  hist_add(histT, k1 >> 24, lane);
        hist_add(histT, (k2 >> 8) & 255u, lane);  hist_add(histT, k2 >> 24, lane);
        hist_add(histT, (k3 >> 8) & 255u, lane);  hist_add(histT, k3 >> 24, lane);
    }
    __syncthreads();

    // ---- suffix-scan the 256 top bins; locate both threshold bins ----
    scanT[tid] = histT[tid];
    __syncthreads();
#pragma unroll
    for (int stp = 1; stp < 256; stp <<= 1) {
        uint32_t v = scanT[tid] + ((tid + stp < 256) ? scanT[tid + stp] : 0u);
        __syncthreads();
        scanT[tid] = v;
        __syncthreads();
    }
    {
        const uint32_t KLO = TWO_N - T_DROP + 1;
        uint32_t mine = scanT[tid];
        uint32_t nxt  = (tid < 255) ? scanT[tid + 1] : 0u;
        if (mine >= T_DROP && nxt < T_DROP) { bc[0] = (uint32_t)tid; bc[1] = T_DROP - nxt; bc[8] = nxt; }
        if (mine >= KLO    && nxt < KLO)    { bc[2] = (uint32_t)tid; bc[3] = KLO - nxt;    bc[9] = nxt; }
    }
    __syncthreads();
    uint32_t dhi = bc[0], khi = bc[1], dlo = bc[2], klo = bc[3];
    uint32_t cntAbove = bc[8];   // # keys with top byte > dhi
    uint32_t cntAboveLo = bc[9]; // # keys with top byte > dlo

    float invtau = 1.0f / *tau_ptr;

    // ---- sweep 1 (fused): middle exp-sum + boundary low hists + stash ----
    float midsum = 0.0f;
    for (int i = tid; i < TWO_N / 8; i += 256) {
        uint4 w = reinterpret_cast<const uint4*>(keys32)[i];
#pragma unroll
        for (int j = 0; j < 4; j++) {
            uint32_t kk = (j == 0) ? w.x : (j == 1) ? w.y : (j == 2) ? w.z : w.w;
#pragma unroll
            for (int hh = 0; hh < 2; hh++) {
                uint32_t u = (hh == 0) ? (kk & 0xFFFFu) : (kk >> 16);
                uint32_t d = u >> 8;
                if (d > dlo && d < dhi) {
                    midsum += __expf(k2f16(u) * invtau);
                } else if (d == dhi || d == dlo) {
                    if (d == dhi) atomicAdd(&lowA[u & 255u], 1u);
                    if (d == dlo) atomicAdd(&lowB[u & 255u], 1u);
                    uint32_t idx = atomicAdd(&nbuf, 1u);
                    if (idx < CAND_CAP) cbuf[idx] = u;
                }
            }
        }
    }
    __syncthreads();

    // ---- low-byte suffix scans (bin dhi, then bin dlo) ----
    scanT[tid] = lowA[tid];
    __syncthreads();
#pragma unroll
    for (int stp = 1; stp < 256; stp <<= 1) {
        uint32_t v = scanT[tid] + ((tid + stp < 256) ? scanT[tid + stp] : 0u);
        __syncthreads();
        scanT[tid] = v;
        __syncthreads();
    }
    {
        uint32_t mine = scanT[tid], nxt = (tid < 255) ? scanT[tid + 1] : 0u;
        if (mine >= khi && nxt < khi) { bc[4] = (dhi << 8) | (uint32_t)tid; bc[6] = mine; }
    }
    __syncthreads();
    scanT[tid] = lowB[tid];
    __syncthreads();
#pragma unroll
    for (int stp = 1; stp < 256; stp <<= 1) {
        uint32_t v = scanT[tid] + ((tid + stp < 256) ? scanT[tid + stp] : 0u);
        __syncthreads();
        scanT[tid] = v;
        __syncthreads();
    }
    {
        uint32_t mine = scanT[tid], nxt = (tid < 255) ? scanT[tid + 1] : 0u;
        if (mine >= klo && nxt < klo) { bc[5] = (dlo << 8) | (uint32_t)tid; bc[7] = nxt; }
    }
    __syncthreads();
    uint32_t vhi = bc[4], vlo = bc[5];
    uint32_t cge = cntAbove + bc[6];                 // #(u >= vhi)
    uint32_t cle = TWO_N - cntAboveLo - bc[7];       // #(u <= vlo)

    // ---- boundary-bin contributions (order-independent u64 fixed point) ----
    unsigned long long part = 0ull;
    uint32_t nb_ = nbuf;
    if (nb_ <= CAND_CAP) {
        for (uint32_t i = tid; i < nb_; i += 256) {
            uint32_t u = cbuf[i];
            if (u > vlo && u < vhi)
                part += (unsigned long long)(__expf(k2f16(u) * invtau) * (float)FIX_SCALE);
        }
    } else {
        for (int i = tid; i < TWO_N / 8; i += 256) {
            uint4 w = reinterpret_cast<const uint4*>(keys32)[i];
#pragma unroll
            for (int j = 0; j < 4; j++) {
                uint32_t kk = (j == 0) ? w.x : (j == 1) ? w.y : (j == 2) ? w.z : w.w;
#pragma unroll
                for (int hh = 0; hh < 2; hh++) {
                    uint32_t u = (hh == 0) ? (kk & 0xFFFFu) : (kk >> 16);
                    uint32_t d = u >> 8;
                    if ((d == dhi || d == dlo) && u > vlo && u < vhi)
                        part += (unsigned long long)(__expf(k2f16(u) * invtau) * (float)FIX_SCALE);
                }
            }
        }
    }

    // ---- reduce: float middle sum + u64 boundary sum ----
#pragma unroll
    for (int o = 16; o; o >>= 1) {
        midsum += __shfl_xor_sync(0xffffffffu, midsum, o);
        part   += __shfl_xor_sync(0xffffffffu, part, o);
    }
    if (lane == 0) { fred[tid >> 5] = midsum; pred_[tid >> 5] = part; }
    __syncthreads();
    if (tid == 0) {
        float s = 0.0f; unsigned long long p = 0ull;
        for (int w = 0; w < 8; w++) { s += fred[w]; p += pred_[w]; }
        s += (float)((double)p * (1.0 / FIX_SCALE));
        s += (float)((int)cge - T_DROP) * __expf(k2f16(vhi) * invtau)
           + (float)((int)cle - T_DROP) * __expf(k2f16(vlo) * invtau);
        g_rowlog[row] = logf(s);
    }
}

// ---------------------------------------------------------------------------
// 4) Final reduction: 32-block partial + 1-warp finish
// ---------------------------------------------------------------------------
__global__ __launch_bounds__(128) void partial_kernel(const float* __restrict__ tau_ptr) {
    int tid = threadIdx.x, b = blockIdx.x;
    int i = b * 128 + tid;
    double invtau = 1.0 / (double)(*tau_ptr);
    double acc = 0.5 * ((double)g_rowlog[i] + (double)g_rowlog[N_ROWS + i])
               - (double)g_diag[i] * invtau;
#pragma unroll
    for (int o = 16; o; o >>= 1) acc += __shfl_xor_sync(0xffffffffu, acc, o);
    __shared__ double dred[4];
    if ((tid & 31) == 0) dred[tid >> 5] = acc;
    __syncthreads();
    if (tid == 0) g_part[b] = dred[0] + dred[1] + dred[2] + dred[3];
}

__global__ void finish_kernel(float* __restrict__ out) {
    int tid = threadIdx.x;  // 32
    double acc = g_part[tid];
#pragma unroll
    for (int o = 16; o; o >>= 1) acc += __shfl_xor_sync(0xffffffffu, acc, o);
    if (tid == 0) out[0] = (float)(acc / (double)N_ROWS);
}

// ---------------------------------------------------------------------------
extern "C" void kernel_launch(void* const* d_in, const int* in_sizes, int n_in,
                              void* d_out, int out_size) {
    const float* h1  = (const float*)d_in[0];
    const float* h2  = (const float*)d_in[1];
    const float* tau = (const float*)d_in[3];
    float* out = (float*)d_out;

    cudaFuncSetAttribute(gram_mma_kernel, cudaFuncAttributeMaxDynamicSharedMemorySize, SMEM_GEMM);

    normalize_kernel<<<TWO_N / 2, 128>>>(h1, h2);
    gram_mma_kernel<<<dim3(64, 64), 256, SMEM_GEMM>>>();
    row_select_kernel<<<TWO_N, 256>>>(tau);
    partial_kernel<<<32, 128>>>(tau);
    finish_kernel<<<1, 32>>>(out);
}

// round 9
// speedup vs baseline: 1.1458x; 1.1336x over previous
#include <cuda_runtime.h>
#include <cuda_fp16.h>
#include <cuda_bf16.h>
#include <cstdint>
#include <cstddef>

#define N_ROWS 4096
#define D 512
#define TWO_N 8192
#define T_DROP 409
#define CHUNKS 8              // 512 / 64 K-elems per chunk
#define PANEL_BYTES 16384     // 128 rows x 128 bytes (64 bf16)

// ---------------- device scratch (allocation-free rule) ----------------
__device__ __align__(1024) uint16_t g_Gp[(size_t)TWO_N * D];      // bf16 SW128 panels (8 MB)
__device__ __align__(16)   uint16_t g_S16[(size_t)TWO_N * TWO_N]; // fp16 Gram (128 MB)
__device__ float g_rowlog[TWO_N];
__device__ float g_diag[N_ROWS];                                  // S[i, 4096+i]
__device__ double g_part[32];

// ---------------- PTX helpers ----------------
__device__ __forceinline__ uint32_t smem_u32(const void* p) {
    uint32_t a;
    asm("{ .reg .u64 t; cvta.to.shared.u64 t, %1; cvt.u32.u64 %0, t; }" : "=r"(a) : "l"(p));
    return a;
}
__device__ __forceinline__ void cp16(uint32_t saddr, const void* g) {
    asm volatile("cp.async.cg.shared.global [%0], [%1], 16;" :: "r"(saddr), "l"(g));
}
__device__ __forceinline__ void cp_commit() {
    asm volatile("cp.async.commit_group;" ::: "memory");
}
template <int N> __device__ __forceinline__ void cp_wait() {
    asm volatile("cp.async.wait_group %0;" :: "n"(N) : "memory");
}
__device__ __forceinline__ void ldsm4(uint32_t* r, uint32_t addr) {
    asm volatile("ldmatrix.sync.aligned.m8n8.x4.shared.b16 {%0,%1,%2,%3}, [%4];"
                 : "=r"(r[0]), "=r"(r[1]), "=r"(r[2]), "=r"(r[3]) : "r"(addr));
}
__device__ __forceinline__ void mma16816(float* d, const uint32_t* a, const uint32_t* b) {
    asm volatile(
        "mma.sync.aligned.m16n8k16.row.col.f32.bf16.bf16.f32 "
        "{%0,%1,%2,%3}, {%4,%5,%6,%7}, {%8,%9}, {%0,%1,%2,%3};"
        : "+f"(d[0]), "+f"(d[1]), "+f"(d[2]), "+f"(d[3])
        : "r"(a[0]), "r"(a[1]), "r"(a[2]), "r"(a[3]), "r"(b[0]), "r"(b[1]));
}
__device__ __forceinline__ uint32_t swz128(uint32_t off) { return off ^ ((off >> 3) & 0x70); }

// ---------------------------------------------------------------------------
// 1) Row L2-normalize into bf16 SW128-swizzled panels.
// ---------------------------------------------------------------------------
__global__ __launch_bounds__(128) void normalize_kernel(const float* __restrict__ h1,
                                                        const float* __restrict__ h2) {
    int half_ = threadIdx.x >> 6;
    int g     = threadIdx.x & 63;
    int row   = blockIdx.x * 2 + half_;
    const float* src = (row < N_ROWS) ? (h1 + (size_t)row * D)
                                      : (h2 + (size_t)(row - N_ROWS) * D);
    float4 v0 = ((const float4*)src)[g * 2];
    float4 v1 = ((const float4*)src)[g * 2 + 1];
    float ss = v0.x * v0.x + v0.y * v0.y + v0.z * v0.z + v0.w * v0.w
             + v1.x * v1.x + v1.y * v1.y + v1.z * v1.z + v1.w * v1.w;
#pragma unroll
    for (int o = 16; o; o >>= 1) ss += __shfl_xor_sync(0xffffffffu, ss, o);
    __shared__ float ws[4];
    if ((threadIdx.x & 31) == 0) ws[threadIdx.x >> 5] = ss;
    __syncthreads();
    float tot = ws[half_ * 2] + ws[half_ * 2 + 1];
    float inv = 1.0f / fmaxf(sqrtf(tot), 1e-12f);

    __nv_bfloat162 b0 = __floats2bfloat162_rn(v0.x * inv, v0.y * inv);
    __nv_bfloat162 b1 = __floats2bfloat162_rn(v0.z * inv, v0.w * inv);
    __nv_bfloat162 b2 = __floats2bfloat162_rn(v1.x * inv, v1.y * inv);
    __nv_bfloat162 b3 = __floats2bfloat162_rn(v1.z * inv, v1.w * inv);
    uint4 w;
    w.x = *reinterpret_cast<uint32_t*>(&b0);
    w.y = *reinterpret_cast<uint32_t*>(&b1);
    w.z = *reinterpret_cast<uint32_t*>(&b2);
    w.w = *reinterpret_cast<uint32_t*>(&b3);

    int kc = g >> 3, gi = g & 7;
    size_t panel = ((size_t)(row >> 7) * CHUNKS + kc) * PANEL_BYTES;
    uint32_t off = swz128((uint32_t)(row & 127) * 128 + gi * 16);
    *reinterpret_cast<uint4*>(reinterpret_cast<char*>(g_Gp) + panel + off) = w;
}

// ---------------------------------------------------------------------------
// 2) S = G*G^T via mma.sync bf16 (128x128 tiles, symmetric: bx >= by only).
// ---------------------------------------------------------------------------
#define SMEM_GEMM 65536
#define STAGE_LD 130   // fp16 stage tile row stride (conflict-free transpose reads)

__global__ __launch_bounds__(256) void gram_mma_kernel() {
    extern __shared__ __align__(1024) char smc[];
    int bx = blockIdx.x, by = blockIdx.y;
    if (bx < by) return;

    uint32_t sb = smem_u32(smc);
    int tid = threadIdx.x, wid = tid >> 5, lane = tid & 31;
    int mOff = (wid & 3) * 32;     // warp M offset in tile
    int nOff = (wid >> 2) * 64;    // warp N offset in tile

    const char* Ap = reinterpret_cast<const char*>(g_Gp) + (size_t)by * CHUNKS * PANEL_BYTES;
    const char* Bp = reinterpret_cast<const char*>(g_Gp) + (size_t)bx * CHUNKS * PANEL_BYTES;

    auto copy_chunk = [&](int c, int buf) {
        uint32_t sA = sb + buf * 16384;
        uint32_t sB = sb + 32768 + buf * 16384;
        const char* gA = Ap + (size_t)c * PANEL_BYTES;
        const char* gB = Bp + (size_t)c * PANEL_BYTES;
#pragma unroll
        for (int i = 0; i < 4; i++) cp16(sA + (tid + i * 256) * 16, gA + (tid + i * 256) * 16);
#pragma unroll
        for (int i = 0; i < 4; i++) cp16(sB + (tid + i * 256) * 16, gB + (tid + i * 256) * 16);
        cp_commit();
    };

    // Per-lane ldmatrix address components (SW128: XOR = (row&7)*16, 16B granular)
    uint32_t offA[2], xorA[2];
#pragma unroll
    for (int mt = 0; mt < 2; mt++) {
        uint32_t r = mOff + mt * 16 + (lane & 15);
        offA[mt] = r * 128; xorA[mt] = (r & 7) * 16;
    }
    uint32_t colA = (lane >> 4) * 16;
    uint32_t offB[4], xorB[4];
#pragma unroll
    for (int nb = 0; nb < 4; nb++) {
        uint32_t r = nOff + nb * 16 + (lane & 7) + ((lane >> 4) << 3);
        offB[nb] = r * 128; xorB[nb] = (r & 7) * 16;
    }
    uint32_t colB = ((lane >> 3) & 1) * 16;

    float acc[2][8][4];
#pragma unroll
    for (int i = 0; i < 2; i++)
#pragma unroll
        for (int j = 0; j < 8; j++)
#pragma unroll
            for (int k = 0; k < 4; k++) acc[i][j][k] = 0.0f;

    copy_chunk(0, 0);
    copy_chunk(1, 1);

    for (int c = 0; c < CHUNKS; c++) {
        int buf = c & 1;
        if (c < CHUNKS - 1) cp_wait<1>(); else cp_wait<0>();
        __syncthreads();
        uint32_t sA = sb + buf * 16384;
        uint32_t sB = sb + 32768 + buf * 16384;
#pragma unroll
        for (int ks = 0; ks < 4; ks++) {
            uint32_t a[2][4], b[4][4];
#pragma unroll
            for (int mt = 0; mt < 2; mt++)
                ldsm4(a[mt], sA + offA[mt] + (((uint32_t)ks * 32 + colA) ^ xorA[mt]));
#pragma unroll
            for (int nb = 0; nb < 4; nb++)
                ldsm4(b[nb], sB + offB[nb] + (((uint32_t)ks * 32 + colB) ^ xorB[nb]));
#pragma unroll
            for (int mt = 0; mt < 2; mt++)
#pragma unroll
                for (int nb = 0; nb < 4; nb++) {
                    mma16816(acc[mt][nb * 2],     a[mt], &b[nb][0]);
                    mma16816(acc[mt][nb * 2 + 1], a[mt], &b[nb][2]);
                }
        }
        __syncthreads();
        if (c + 2 < CHUNKS) copy_chunk(c + 2, buf);
    }

    // ---- Epilogue: stage fp16 tile in smem, write tile (+ mirror) coalesced ----
    __half* st = reinterpret_cast<__half*>(smc);
    int rr = lane >> 2, cc = (lane & 3) * 2;
#pragma unroll
    for (int mt = 0; mt < 2; mt++)
#pragma unroll
        for (int nt = 0; nt < 8; nt++) {
            int r = mOff + mt * 16 + rr;
            int ccol = nOff + nt * 8 + cc;
            __half2 lo = __floats2half2_rn(acc[mt][nt][0], acc[mt][nt][1]);
            __half2 hi = __floats2half2_rn(acc[mt][nt][2], acc[mt][nt][3]);
            *reinterpret_cast<__half2*>(&st[r * STAGE_LD + ccol]) = lo;
            *reinterpret_cast<__half2*>(&st[(r + 8) * STAGE_LD + ccol]) = hi;
        }
    __syncthreads();

    // diag of s12: tile (by, bx=by+32) holds S[by*128+r][4096+by*128+r] at st[r][r]
    if (bx == by + 32) {
        for (int i = tid; i < 128; i += 256)
            g_diag[by * 128 + i] = __half2float(st[i * STAGE_LD + i]);
    }

    // direct tile: row-major coalesced
    for (int i = tid; i < 128 * 64; i += 256) {
        int r = i >> 6, cw = i & 63;
        uint32_t v = *reinterpret_cast<uint32_t*>(&st[r * STAGE_LD + cw * 2]);
        *reinterpret_cast<uint32_t*>(&g_S16[(size_t)(by * 128 + r) * TWO_N + bx * 128 + cw * 2]) = v;
    }
    if (bx > by) {
        // mirror: out[c][r] = tile[r][c]
        for (int i = tid; i < 128 * 64; i += 256) {
            int c = i >> 6, rw = i & 63;
            __half lo = st[(2 * rw) * STAGE_LD + c];
            __half hi = st[(2 * rw + 1) * STAGE_LD + c];
            __half2 v = __halves2half2(lo, hi);
            *reinterpret_cast<__half2*>(&g_S16[(size_t)(bx * 128 + c) * TWO_N + by * 128 + 2 * rw]) = v;
        }
    }
}

// ---------------------------------------------------------------------------
// 3) Per-row 16-bit radix select + exp-sum (R6 3-sweep structure;
//    counts derived from suffix scans so the exp sweep is exp-only).
// ---------------------------------------------------------------------------
__device__ __forceinline__ uint32_t f2k16x2(uint32_t u) {
    uint32_t s = (u >> 15) & 0x00010001u;
    return u ^ (0x80008000u | (s * 0x7FFFu));
}
__device__ __forceinline__ float k2f16(uint32_t k) {
    uint32_t u = (k & 0x8000u) ? (k & 0x7FFFu) : ((~k) & 0xFFFFu);
    return __half2float(__ushort_as_half((unsigned short)u));
}
__device__ __forceinline__ void hist_add(uint32_t* h, uint32_t d, int lane) {
    unsigned m = __match_any_sync(0xffffffffu, d);
    if ((__ffs(m) - 1) == lane) atomicAdd(&h[d], (uint32_t)__popc(m));
}

__global__ __launch_bounds__(256) void row_select_kernel(const float* __restrict__ tau_ptr) {
    __shared__ __align__(16) uint32_t keys32[TWO_N / 2];   // 16 KB
    __shared__ uint32_t histT[256];
    __shared__ uint32_t scanT[256];
    __shared__ uint32_t lowA[256], lowB[256];
    __shared__ uint32_t bc[12];
    __shared__ float fred[8];
    int row = blockIdx.x, tid = threadIdx.x, lane = tid & 31;
    const uint4* rp4 = reinterpret_cast<const uint4*>(g_S16 + (size_t)row * TWO_N);

    histT[tid] = 0; lowA[tid] = 0; lowB[tid] = 0;
    __syncthreads();

    // ---- sweep 0: load + convert + store + top-byte histogram ----
    for (int i = tid; i < TWO_N / 8; i += 256) {
        uint4 w = rp4[i];
        uint32_t k0 = f2k16x2(w.x), k1 = f2k16x2(w.y), k2 = f2k16x2(w.z), k3 = f2k16x2(w.w);
        reinterpret_cast<uint4*>(keys32)[i] = make_uint4(k0, k1, k2, k3);
        hist_add(histT, (k0 >> 8) & 255u, lane);  hist_add(histT, k0 >> 24, lane);
        hist_add(histT, (k1 >> 8) & 255u, lane);  hist_add(histT, k1 >> 24, lane);
        hist_add(histT, (k2 >> 8) & 255u, lane);  hist_add(histT, k2 >> 24, lane);
        hist_add(histT, (k3 >> 8) & 255u, lane);  hist_add(histT, k3 >> 24, lane);
    }
    __syncthreads();

    // ---- suffix-scan the 256 top bins; locate both threshold bins ----
    scanT[tid] = histT[tid];
    __syncthreads();
#pragma unroll
    for (int stp = 1; stp < 256; stp <<= 1) {
        uint32_t v = scanT[tid] + ((tid + stp < 256) ? scanT[tid + stp] : 0u);
        __syncthreads();
        scanT[tid] = v;
        __syncthreads();
    }
    {
        const uint32_t KLO = TWO_N - T_DROP + 1;
        uint32_t mine = scanT[tid];
        uint32_t nxt  = (tid < 255) ? scanT[tid + 1] : 0u;
        if (mine >= T_DROP && nxt < T_DROP) { bc[0] = (uint32_t)tid; bc[1] = T_DROP - nxt; bc[8] = nxt; }
        if (mine >= KLO    && nxt < KLO)    { bc[2] = (uint32_t)tid; bc[3] = KLO - nxt;    bc[9] = nxt; }
    }
    __syncthreads();
    uint32_t dhi = bc[0], khi = bc[1], dlo = bc[2], klo = bc[3];
    uint32_t cntAbove = bc[8];    // # keys with top byte > dhi
    uint32_t cntAboveLo = bc[9];  // # keys with top byte > dlo

    // ---- sweep 1: low-byte hists for both candidate bins (branch-light) ----
    for (int i = tid; i < TWO_N / 8; i += 256) {
        uint4 w = reinterpret_cast<const uint4*>(keys32)[i];
#pragma unroll
        for (int j = 0; j < 4; j++) {
            uint32_t kk = (j == 0) ? w.x : (j == 1) ? w.y : (j == 2) ? w.z : w.w;
#pragma unroll
            for (int hh = 0; hh < 2; hh++) {
                uint32_t u = (hh == 0) ? (kk & 0xFFFFu) : (kk >> 16);
                uint32_t tb = u >> 8;
                if (tb == dhi) atomicAdd(&lowA[u & 0xFFu], 1u);
                if (tb == dlo) atomicAdd(&lowB[u & 0xFFu], 1u);
            }
        }
    }
    __syncthreads();

    // ---- low-byte suffix scans (bin dhi, then bin dlo) ----
    scanT[tid] = lowA[tid];
    __syncthreads();
#pragma unroll
    for (int stp = 1; stp < 256; stp <<= 1) {
        uint32_t v = scanT[tid] + ((tid + stp < 256) ? scanT[tid + stp] : 0u);
        __syncthreads();
        scanT[tid] = v;
        __syncthreads();
    }
    {
        uint32_t mine = scanT[tid], nxt = (tid < 255) ? scanT[tid + 1] : 0u;
        if (mine >= khi && nxt < khi) { bc[4] = (dhi << 8) | (uint32_t)tid; bc[6] = mine; }
    }
    __syncthreads();
    scanT[tid] = lowB[tid];
    __syncthreads();
#pragma unroll
    for (int stp = 1; stp < 256; stp <<= 1) {
        uint32_t v = scanT[tid] + ((tid + stp < 256) ? scanT[tid + stp] : 0u);
        __syncthreads();
        scanT[tid] = v;
        __syncthreads();
    }
    {
        uint32_t mine = scanT[tid], nxt = (tid < 255) ? scanT[tid + 1] : 0u;
        if (mine >= klo && nxt < klo) { bc[5] = (dlo << 8) | (uint32_t)tid; bc[7] = nxt; }
    }
    __syncthreads();
    uint32_t vhi = bc[4], vlo = bc[5];
    uint32_t cge = cntAbove + bc[6];                 // #(u >= vhi), scan-derived
    uint32_t cle = TWO_N - cntAboveLo - bc[7];       // #(u <= vlo), scan-derived

    // ---- sweep 2: strict-middle exp-sum only (no counters) ----
    float invtau = 1.0f / *tau_ptr;
    float sum = 0.0f;
    for (int i = tid; i < TWO_N / 8; i += 256) {
        uint4 w = reinterpret_cast<const uint4*>(keys32)[i];
#pragma unroll
        for (int j = 0; j < 4; j++) {
            uint32_t kk = (j == 0) ? w.x : (j == 1) ? w.y : (j == 2) ? w.z : w.w;
#pragma unroll
            for (int hh = 0; hh < 2; hh++) {
                uint32_t u = (hh == 0) ? (kk & 0xFFFFu) : (kk >> 16);
                if (u < vhi && u > vlo) sum += __expf(k2f16(u) * invtau);
            }
        }
    }
#pragma unroll
    for (int o = 16; o; o >>= 1) sum += __shfl_xor_sync(0xffffffffu, sum, o);
    if (lane == 0) fred[tid >> 5] = sum;
    __syncthreads();
    if (tid == 0) {
        float s = 0.0f;
        for (int w = 0; w < 8; w++) s += fred[w];
        s += (float)((int)cge - T_DROP) * __expf(k2f16(vhi) * invtau)
           + (float)((int)cle - T_DROP) * __expf(k2f16(vlo) * invtau);
        g_rowlog[row] = logf(s);
    }
}

// ---------------------------------------------------------------------------
// 4) Final reduction: 32-block partial + 1-warp finish
// ---------------------------------------------------------------------------
__global__ __launch_bounds__(128) void partial_kernel(const float* __restrict__ tau_ptr) {
    int tid = threadIdx.x, b = blockIdx.x;
    int i = b * 128 + tid;
    double invtau = 1.0 / (double)(*tau_ptr);
    double acc = 0.5 * ((double)g_rowlog[i] + (double)g_rowlog[N_ROWS + i])
               - (double)g_diag[i] * invtau;
#pragma unroll
    for (int o = 16; o; o >>= 1) acc += __shfl_xor_sync(0xffffffffu, acc, o);
    __shared__ double dred[4];
    if ((tid & 31) == 0) dred[tid >> 5] = acc;
    __syncthreads();
    if (tid == 0) g_part[b] = dred[0] + dred[1] + dred[2] + dred[3];
}

__global__ void finish_kernel(float* __restrict__ out) {
    int tid = threadIdx.x;  // 32
    double acc = g_part[tid];
#pragma unroll
    for (int o = 16; o; o >>= 1) acc += __shfl_xor_sync(0xffffffffu, acc, o);
    if (tid == 0) out[0] = (float)(acc / (double)N_ROWS);
}

// ---------------------------------------------------------------------------
extern "C" void kernel_launch(void* const* d_in, const int* in_sizes, int n_in,
                              void* d_out, int out_size) {
    const float* h1  = (const float*)d_in[0];
    const float* h2  = (const float*)d_in[1];
    const float* tau = (const float*)d_in[3];
    float* out = (float*)d_out;

    cudaFuncSetAttribute(gram_mma_kernel, cudaFuncAttributeMaxDynamicSharedMemorySize, SMEM_GEMM);

    normalize_kernel<<<TWO_N / 2, 128>>>(h1, h2);
    gram_mma_kernel<<<dim3(64, 64), 256, SMEM_GEMM>>>();
    row_select_kernel<<<TWO_N, 256>>>(tau);
    partial_kernel<<<32, 128>>>(tau);
    finish_kernel<<<1, 32>>>(out);
}